// round 8
// baseline (speedup 1.0000x reference)
#include <cuda_runtime.h>
#include <cuda_bf16.h>
#include <cstdint>

typedef unsigned long long ull;

#define BB 64
#define NN 1700
#define CC 256
#define MAXE 16384
#define MTOT (BB*NN)
#define MTILES (MTOT/128)          // 850
#define NSM 148

// ---------------- scratch (device globals; no allocation allowed) ----------------
__device__ float g_h[(size_t)BB*NN*CC];                    // GEMM output (fp32)
__device__ __nv_bfloat16 g_ah[(size_t)MTOT*CC];            // A hi image (chunked+swizzled)
__device__ __nv_bfloat16 g_al[(size_t)MTOT*CC];            // A lo image
__device__ __nv_bfloat16 g_bh[3*65536];                    // B hi images per layer
__device__ __nv_bfloat16 g_bl[3*65536];                    // B lo images per layer
__device__ int   g_ptr[2*(NN+1)];
__device__ float g_dinv[2*NN];
__device__ int   g_esrc[2*MAXE];
__device__ float g_enorm[2*MAXE];

// ---------------- PTX helpers (all sm_80-class: valid for compute_103) ----------------
__device__ __forceinline__ uint32_t smem_u32(const void* p) {
    uint32_t a;
    asm("{ .reg .u64 t; cvta.to.shared.u64 t, %1; cvt.u32.u64 %0, t; }" : "=r"(a) : "l"(p));
    return a;
}
#define LDSM4(r0,r1,r2,r3,addr) \
    asm volatile("ldmatrix.sync.aligned.m8n8.x4.shared.b16 {%0,%1,%2,%3}, [%4];" \
        : "=r"(r0),"=r"(r1),"=r"(r2),"=r"(r3) : "r"(addr))
#define MMA16816(d, a, b0, b1) \
    asm volatile("mma.sync.aligned.m16n8k16.row.col.f32.bf16.bf16.f32 " \
        "{%0,%1,%2,%3},{%4,%5,%6,%7},{%8,%9},{%0,%1,%2,%3};" \
        : "+f"((d)[0]),"+f"((d)[1]),"+f"((d)[2]),"+f"((d)[3]) \
        : "r"((a)[0]),"r"((a)[1]),"r"((a)[2]),"r"((a)[3]), "r"(b0),"r"(b1))
#define CPASYNC16(dst, src) \
    asm volatile("cp.async.cg.shared.global [%0], [%1], 16;" :: "r"(dst), "l"(src))
#define CPCOMMIT() asm volatile("cp.async.commit_group;")
#define CPWAIT(n)  asm volatile("cp.async.wait_group %0;" :: "n"(n))

// chunked image element offset within a 128x32 block, 16B-chunk XOR swizzle:
// row r (0..127, 64B/row), kin (0..31): kc' = (kin>>3) ^ ((r>>1)&3)
__device__ __forceinline__ uint32_t swz_elem(int r, int kin) {
    return (uint32_t)(r*32 + ((((kin>>3) ^ ((r>>1)&3)))<<3) + (kin&7));
}

// ---------------- fused prep: histogram -> scan -> dinv -> CSR fill, both edge sets ----------------
__global__ __launch_bounds__(1024) void k_prep(const int* __restrict__ sp, int Esp,
                                               const int* __restrict__ tm, int Etm) {
    __shared__ int   cnt[2*NN];
    __shared__ float dv [2*NN];
    __shared__ int   sbuf[2048];
    int t = threadIdx.x;
    for (int i = t; i < 2*NN; i += 1024) cnt[i] = 0;
    __syncthreads();
    const int* spc = sp + Esp;
    const int* tmc = tm + Etm;
    for (int e = t; e < Esp; e += 1024) atomicAdd(&cnt[spc[e]], 1);
    for (int e = t; e < Etm; e += 1024) atomicAdd(&cnt[NN + tmc[e]], 1);
    __syncthreads();
    for (int i = t; i < 2*NN; i += 1024) {
        float d = rsqrtf((float)(cnt[i] + 1));     // +1 self loop
        dv[i] = d; g_dinv[i] = d;
    }
    // exclusive scans (one per set)
    for (int set = 0; set < 2; set++) {
        __syncthreads();
        for (int i = t; i < 2048; i += 1024) sbuf[i] = (i < NN) ? cnt[set*NN + i] : 0;
        __syncthreads();
        for (int off = 1; off < 2048; off <<= 1) {
            int v0 = (t >= off) ? sbuf[t - off] : 0;
            int i1 = t + 1024;
            int v1 = sbuf[i1 - off];
            __syncthreads();
            sbuf[t] += v0; sbuf[i1] += v1;
            __syncthreads();
        }
        int* ptr = g_ptr + set*(NN+1);
        for (int i = t; i <= NN; i += 1024) ptr[i] = (i == 0) ? 0 : sbuf[i-1];
    }
    __syncthreads();
    for (int i = t; i < 2*NN; i += 1024) cnt[i] = 0;   // reuse as cursors
    __syncthreads();
    for (int e = t; e < Esp; e += 1024) {
        int r = sp[e], c = spc[e];
        float nrm = dv[r] * dv[c];
        int pos = g_ptr[c] + atomicAdd(&cnt[c], 1);
        g_esrc[pos] = r; g_enorm[pos] = nrm;
    }
    for (int e = t; e < Etm; e += 1024) {
        int r = tm[e], c = tmc[e];
        float nrm = dv[NN + r] * dv[NN + c];
        int pos = g_ptr[(NN+1) + c] + atomicAdd(&cnt[NN + c], 1);
        g_esrc[MAXE + pos] = r; g_enorm[MAXE + pos] = nrm;
    }
}

// ---------------- bf16 hi/lo split ----------------
__device__ __forceinline__ void split4(float4 v, uint2& hi, uint2& lo) {
    __nv_bfloat16 h0 = __float2bfloat16(v.x), h1 = __float2bfloat16(v.y),
                  h2 = __float2bfloat16(v.z), h3 = __float2bfloat16(v.w);
    __nv_bfloat16 l0 = __float2bfloat16(v.x - __bfloat162float(h0));
    __nv_bfloat16 l1 = __float2bfloat16(v.y - __bfloat162float(h1));
    __nv_bfloat16 l2 = __float2bfloat16(v.z - __bfloat162float(h2));
    __nv_bfloat16 l3 = __float2bfloat16(v.w - __bfloat162float(h3));
    __nv_bfloat162 hA = __nv_bfloat162(h0, h1), hB = __nv_bfloat162(h2, h3);
    __nv_bfloat162 lA = __nv_bfloat162(l0, l1), lB = __nv_bfloat162(l2, l3);
    hi.x = *(uint32_t*)&hA; hi.y = *(uint32_t*)&hB;
    lo.x = *(uint32_t*)&lA; lo.y = *(uint32_t*)&lB;
}

// x fp32 [M,256] -> hi/lo images: [tile][chunk(8)][128x32 swizzled]
__global__ __launch_bounds__(256) void k_convA(const float* __restrict__ X) {
    int idx = blockIdx.x * 256 + threadIdx.x;
    int m = idx >> 6, lane = idx & 63;
    if (m >= MTOT) return;
    int k = lane * 4;
    float4 v = *(const float4*)&X[(size_t)m * CC + k];
    uint2 hi, lo; split4(v, hi, lo);
    int tile = m >> 7, mi = m & 127, chunk = k >> 5, kin = k & 31;
    size_t eo = (size_t)(tile*8 + chunk)*4096 + swz_elem(mi, kin);
    *(uint2*)(g_ah + eo) = hi;
    *(uint2*)(g_al + eo) = lo;
}

// all three W fp32 [k=256][n=256] -> hi/lo images (layer = blockIdx.x/64)
__global__ __launch_bounds__(256) void k_convW3(const float* __restrict__ W1,
                                                const float* __restrict__ W2,
                                                const float* __restrict__ W3) {
    int layer = blockIdx.x >> 6;
    const float* W = (layer == 0) ? W1 : ((layer == 1) ? W2 : W3);
    int idx = (blockIdx.x & 63) * 256 + threadIdx.x;
    int n = idx >> 6, kq = idx & 63;
    if (n >= 256) return;
    int k = kq * 4;
    float4 v = make_float4(W[(size_t)(k+0)*CC + n], W[(size_t)(k+1)*CC + n],
                           W[(size_t)(k+2)*CC + n], W[(size_t)(k+3)*CC + n]);
    uint2 hi, lo; split4(v, hi, lo);
    int nh = n >> 7, ni = n & 127, chunk = k >> 5, kin = k & 31;
    size_t eo = (size_t)layer*65536 + (size_t)(nh*8 + chunk)*4096 + swz_elem(ni, kin);
    *(uint2*)(g_bh + eo) = hi;
    *(uint2*)(g_bl + eo) = lo;
}

// ---------------- persistent HMMA GEMM: H = A @ W via bf16 3-product split ----------------
// grid (148): each CTA loops tiles bid, bid+148, ...; cp.async chunk stream is
// continuous across tile boundaries (4 buffers, single barrier per chunk).
// CTA tile 128x256, 512 thr = 16 warps (4m x 4n), warp tile 32x64.
#define GSTAGE 49152
#define GSM (4*GSTAGE)
__global__ __launch_bounds__(512) void k_gemm_mma(const __nv_bfloat16* __restrict__ Bh,
                                                  const __nv_bfloat16* __restrict__ Bl,
                                                  float* __restrict__ H) {
    extern __shared__ __align__(128) char smc[];
    uint32_t sb = smem_u32(smc);
    int tid = threadIdx.x, wid = tid >> 5, lane = tid & 31;
    int bid = blockIdx.x;
    int mwarp = (wid >> 2) * 32, nwarp = (wid & 3) * 64;

    int nt = (MTILES - bid + NSM - 1) / NSM;   // tiles for this CTA
    int total = nt * 8;                        // global chunk count

    const char* gBh = (const char*)Bh;
    const char* gBl = (const char*)Bl;

    // ldmatrix address precompute
    int r15 = lane & 15, hi2 = lane >> 4;
    uint32_t aoff[2]; int asw[2];
    #pragma unroll
    for (int i = 0; i < 2; i++) {
        int mr = mwarp + i*16 + r15;
        aoff[i] = mr * 64; asw[i] = (mr >> 1) & 3;
    }
    uint32_t boff[4]; int bsw[4];
    uint32_t nhbase = (uint32_t)(nwarp >> 7) * 8192;
    #pragma unroll
    for (int j = 0; j < 4; j++) {
        int nr = (nwarp & 127) + j*16 + r15;
        boff[j] = nhbase + nr * 64; bsw[j] = (nr >> 1) & 3;
    }

    float d[2][8][4];
    #pragma unroll
    for (int i = 0; i < 2; i++)
        #pragma unroll
        for (int j = 0; j < 8; j++)
            #pragma unroll
            for (int q = 0; q < 4; q++) d[i][j][q] = 0.f;

    // issue chunk g: tile = bid + (g>>3)*148, chunk c = g&7, buffer g&3
    #define ISSUEG(g) do { \
        int _c = (g) & 7; \
        size_t _tb = (size_t)(bid + ((g) >> 3) * NSM) * 65536 + (size_t)_c * 8192; \
        uint32_t so = sb + (uint32_t)((g) & 3) * GSTAGE; \
        uint32_t off = (uint32_t)tid * 16; \
        CPASYNC16(so +        off, (const char*)g_ah + _tb + off); \
        CPASYNC16(so + 8192 + off, (const char*)g_al + _tb + off); \
        _Pragma("unroll") \
        for (int nh_ = 0; nh_ < 2; nh_++) { \
            size_t gb = (size_t)(nh_*8 + _c) * 8192; \
            CPASYNC16(so + 16384 + nh_*8192 + off, gBh + gb + off); \
            CPASYNC16(so + 32768 + nh_*8192 + off, gBl + gb + off); \
        } \
        CPCOMMIT(); \
    } while (0)

    ISSUEG(0);
    if (total > 1) ISSUEG(1);
    if (total > 2) ISSUEG(2);
    for (int g = 0; g < total; g++) {
        int rem = total - g - 1;
        if (rem >= 2)      { CPWAIT(2); }
        else if (rem == 1) { CPWAIT(1); }
        else               { CPWAIT(0); }
        __syncthreads();                       // single barrier per chunk
        uint32_t base = sb + (uint32_t)(g & 3) * GSTAGE;
        #pragma unroll
        for (int s = 0; s < 2; s++) {
            uint32_t ah[2][4], al[2][4];
            #pragma unroll
            for (int i = 0; i < 2; i++) {
                uint32_t kc = (uint32_t)((((s<<1)|hi2) ^ asw[i]) << 4);
                LDSM4(ah[i][0],ah[i][1],ah[i][2],ah[i][3], base + aoff[i] + kc);
                LDSM4(al[i][0],al[i][1],al[i][2],al[i][3], base + 8192 + aoff[i] + kc);
            }
            #pragma unroll
            for (int jp = 0; jp < 2; jp++) {
                uint32_t bh[2][4], bl[2][4];
                #pragma unroll
                for (int q = 0; q < 2; q++) {
                    int j = jp*2 + q;
                    uint32_t kc = (uint32_t)((((s<<1)|hi2) ^ bsw[j]) << 4);
                    LDSM4(bh[q][0],bh[q][1],bh[q][2],bh[q][3], base + 16384 + boff[j] + kc);
                    LDSM4(bl[q][0],bl[q][1],bl[q][2],bl[q][3], base + 32768 + boff[j] + kc);
                }
                #pragma unroll
                for (int q = 0; q < 2; q++)
                    #pragma unroll
                    for (int i = 0; i < 2; i++) {
                        MMA16816(d[i][4*jp+2*q],   ah[i], bh[q][0], bh[q][2]);
                        MMA16816(d[i][4*jp+2*q+1], ah[i], bh[q][1], bh[q][3]);
                    }
                #pragma unroll
                for (int q = 0; q < 2; q++)
                    #pragma unroll
                    for (int i = 0; i < 2; i++) {
                        MMA16816(d[i][4*jp+2*q],   ah[i], bl[q][0], bl[q][2]);
                        MMA16816(d[i][4*jp+2*q+1], ah[i], bl[q][1], bl[q][3]);
                    }
                #pragma unroll
                for (int q = 0; q < 2; q++)
                    #pragma unroll
                    for (int i = 0; i < 2; i++) {
                        MMA16816(d[i][4*jp+2*q],   al[i], bh[q][0], bh[q][2]);
                        MMA16816(d[i][4*jp+2*q+1], al[i], bh[q][1], bh[q][3]);
                    }
            }
        }
        if (g + 3 < total) ISSUEG(g+3);        // writes buf (g-1)&3: safe past this barrier
        if ((g & 7) == 7) {
            // epilogue for finished tile (overlaps in-flight cp.async of next tile)
            int tile = bid + (g >> 3) * NSM;
            int rr = lane >> 2, cp = (lane & 3) * 2;
            #pragma unroll
            for (int i = 0; i < 2; i++) {
                size_t row = (size_t)tile*128 + mwarp + i*16 + rr;
                #pragma unroll
                for (int j = 0; j < 8; j++) {
                    int col = nwarp + j*8 + cp;
                    *(float2*)&H[row*CC + col]     = make_float2(d[i][j][0], d[i][j][1]);
                    *(float2*)&H[(row+8)*CC + col] = make_float2(d[i][j][2], d[i][j][3]);
                }
            }
            #pragma unroll
            for (int i = 0; i < 2; i++)
                #pragma unroll
                for (int j = 0; j < 8; j++)
                    #pragma unroll
                    for (int q = 0; q < 4; q++) d[i][j][q] = 0.f;
        }
    }
}

// ---------------- aggregation ----------------
// acc = sum_in-edges norm*h[b,src,:] + dinv^2*h[b,n,:] + bias (+res), relu.
// block = 1 node x 4 batches (metadata shared); write_img -> hi/lo A images.
__global__ __launch_bounds__(256) void k_agg(const float* __restrict__ h, int set,
                                             const float* __restrict__ bias,
                                             const float* __restrict__ residual,
                                             float* __restrict__ out, int write_img) {
    int g    = threadIdx.x >> 6;           // batch sub-group 0..3
    int lane = threadIdx.x & 63;           // channel/4
    int n = blockIdx.x;
    int b = blockIdx.y * 4 + g;

    const int* ptr = g_ptr + set*(NN+1);
    int p0 = __ldg(&ptr[n]), p1 = __ldg(&ptr[n+1]);
    float dn = __ldg(&g_dinv[set*NN + n]);
    size_t bbase = (size_t)b * NN;
    size_t base  = (bbase + n) * CC + lane*4;

    float4 sv = *(const float4*)&h[base];
    float w = dn * dn;
    float4 acc;
    acc.x = w*sv.x; acc.y = w*sv.y; acc.z = w*sv.z; acc.w = w*sv.w;

    int off = set*MAXE;
    int j = p0;
    for (; j + 4 <= p1; j += 4) {
        int   s0 = __ldg(&g_esrc [off + j]);
        int   s1 = __ldg(&g_esrc [off + j + 1]);
        int   s2 = __ldg(&g_esrc [off + j + 2]);
        int   s3 = __ldg(&g_esrc [off + j + 3]);
        float w0 = __ldg(&g_enorm[off + j]);
        float w1 = __ldg(&g_enorm[off + j + 1]);
        float w2 = __ldg(&g_enorm[off + j + 2]);
        float w3 = __ldg(&g_enorm[off + j + 3]);
        float4 v0 = *(const float4*)&h[(bbase + s0)*CC + lane*4];
        float4 v1 = *(const float4*)&h[(bbase + s1)*CC + lane*4];
        float4 v2 = *(const float4*)&h[(bbase + s2)*CC + lane*4];
        float4 v3 = *(const float4*)&h[(bbase + s3)*CC + lane*4];
        acc.x += w0*v0.x + w1*v1.x + w2*v2.x + w3*v3.x;
        acc.y += w0*v0.y + w1*v1.y + w2*v2.y + w3*v3.y;
        acc.z += w0*v0.z + w1*v1.z + w2*v2.z + w3*v3.z;
        acc.w += w0*v0.w + w1*v1.w + w2*v2.w + w3*v3.w;
    }
    for (; j < p1; ++j) {
        int   s0 = __ldg(&g_esrc [off + j]);
        float w0 = __ldg(&g_enorm[off + j]);
        float4 v0 = *(const float4*)&h[(bbase + s0)*CC + lane*4];
        acc.x += w0*v0.x; acc.y += w0*v0.y; acc.z += w0*v0.z; acc.w += w0*v0.w;
    }

    float4 bi = *(const float4*)&bias[lane*4];
    acc.x += bi.x; acc.y += bi.y; acc.z += bi.z; acc.w += bi.w;
    if (residual) {
        float4 rv = *(const float4*)&residual[base];
        acc.x += rv.x; acc.y += rv.y; acc.z += rv.z; acc.w += rv.w;
    }
    acc.x = fmaxf(acc.x, 0.f); acc.y = fmaxf(acc.y, 0.f);
    acc.z = fmaxf(acc.z, 0.f); acc.w = fmaxf(acc.w, 0.f);

    if (write_img) {
        uint2 hi, lo; split4(acc, hi, lo);
        int m = (int)(bbase + n);
        int tile = m >> 7, mi = m & 127, k = lane*4, chunk = k >> 5, kin = k & 31;
        size_t eo = (size_t)(tile*8 + chunk)*4096 + swz_elem(mi, kin);
        *(uint2*)(g_ah + eo) = hi;
        *(uint2*)(g_al + eo) = lo;
    } else {
        *(float4*)&out[base] = acc;
    }
}

// ---------------- launch ----------------
extern "C" void kernel_launch(void* const* d_in, const int* in_sizes, int n_in,
                              void* d_out, int out_size) {
    const float* x  = (const float*)d_in[0];
    const float* W1 = (const float*)d_in[1];
    const float* b1 = (const float*)d_in[2];
    const float* W2 = (const float*)d_in[3];
    const float* b2 = (const float*)d_in[4];
    const float* W3 = (const float*)d_in[5];
    const float* b3 = (const float*)d_in[6];
    const int*   sp = (const int*)d_in[7];
    const int*   tm = (const int*)d_in[8];
    int Esp = in_sizes[7] / 2;
    int Etm = in_sizes[8] / 2;
    float* out = (float*)d_out;

    float* h; __nv_bfloat16 *bh, *bl;
    cudaGetSymbolAddress((void**)&h,  g_h);
    cudaGetSymbolAddress((void**)&bh, g_bh);
    cudaGetSymbolAddress((void**)&bl, g_bl);

    cudaFuncSetAttribute(k_gemm_mma, cudaFuncAttributeMaxDynamicSharedMemorySize, GSM);

    dim3 ga(NN, BB/4);                // (1700, 16)

    k_convA <<<(MTOT*64 + 255)/256, 256>>>(x);
    k_convW3<<<192, 256>>>(W1, W2, W3);
    k_prep  <<<1, 1024>>>(sp, Esp, tm, Etm);

    // conv1 (4th launch — profiled by ncu)
    k_gemm_mma<<<NSM, 512, GSM>>>(bh, bl, h);
    k_agg<<<ga, 256>>>(h, 0, b1, nullptr, nullptr, 1);
    // conv2
    k_gemm_mma<<<NSM, 512, GSM>>>(bh + 65536, bl + 65536, h);
    k_agg<<<ga, 256>>>(h, 1, b2, nullptr, nullptr, 1);
    // conv3
    k_gemm_mma<<<NSM, 512, GSM>>>(bh + 2*65536, bl + 2*65536, h);
    k_agg<<<ga, 256>>>(h, 0, b3, x, out, 0);
}